// round 5
// baseline (speedup 1.0000x reference)
#include <cuda_runtime.h>
#include <math.h>

#define D 256
#define MAX_N 65536
#define EXP_CUT (-87.0f)   // exp underflow cut
#define CAP 16384          // global candidate list capacity
#define SCAP 2048          // shared survivor list capacity

// Persistent device scratch.
__device__ float        g_vp[4][D];   // 4 partial sums of v = W^T a
__device__ float        g_p[MAX_N];   // p[n] = x[n] . v
__device__ unsigned int g_max_enc;    // order-preserving encoded global max
__device__ int          g_nsurv;      // # candidate edges
__device__ int          g_surv[CAP];  // candidate edge ids
__device__ float        g_sval[CAP];  // candidate scores

__device__ __forceinline__ unsigned int enc_f(float f) {
    unsigned int u = __float_as_uint(f);
    return (u & 0x80000000u) ? ~u : (u | 0x80000000u);
}
__device__ __forceinline__ float dec_f(unsigned int u) {
    return __uint_as_float((u & 0x80000000u) ? (u & 0x7FFFFFFFu) : ~u);
}
#define ENC_NEG_INF 0x007FFFFFu   // enc_f(-inf)

__device__ __forceinline__ float lrelu(float s) { return s > 0.f ? s : 0.2f * s; }

// K0: 4 blocks, each computes a 64-row partial of v[i] = sum_o a[o]*W[o,i].
__global__ void k_init(const float* __restrict__ W, const float* __restrict__ a) {
    int i   = threadIdx.x;           // 0..255
    int seg = blockIdx.x;            // 0..3
    float s = 0.f;
    int o0 = seg * 64;
    #pragma unroll 8
    for (int o = o0; o < o0 + 64; ++o) s = fmaf(__ldg(a + o), __ldg(W + o * D + i), s);
    g_vp[seg][i] = s;
    if (seg == 0 && i == 0) { g_max_enc = ENC_NEG_INF; g_nsurv = 0; }
}

// K1: one warp per node — p[n] = x[n] . v  (v = sum of 4 cached partials).
__global__ void k_dot(const float* __restrict__ x, int N) {
    int w = (blockIdx.x * blockDim.x + threadIdx.x) >> 5;
    if (w >= N) return;
    int lane = threadIdx.x & 31;
    const float4* xr = (const float4*)(x + (size_t)w * D);
    float4 x0 = xr[lane], x1 = xr[lane + 32];

    const float4* vp0 = (const float4*)g_vp[0];
    const float4* vp1 = (const float4*)g_vp[1];
    const float4* vp2 = (const float4*)g_vp[2];
    const float4* vp3 = (const float4*)g_vp[3];
    float4 a0 = vp0[lane],      b0 = vp1[lane],      c0 = vp2[lane],      d0 = vp3[lane];
    float4 a1 = vp0[lane + 32], b1 = vp1[lane + 32], c1 = vp2[lane + 32], d1 = vp3[lane + 32];
    float4 v0, v1;
    v0.x = (a0.x + b0.x) + (c0.x + d0.x);
    v0.y = (a0.y + b0.y) + (c0.y + d0.y);
    v0.z = (a0.z + b0.z) + (c0.z + d0.z);
    v0.w = (a0.w + b0.w) + (c0.w + d0.w);
    v1.x = (a1.x + b1.x) + (c1.x + d1.x);
    v1.y = (a1.y + b1.y) + (c1.y + d1.y);
    v1.z = (a1.z + b1.z) + (c1.z + d1.z);
    v1.w = (a1.w + b1.w) + (c1.w + d1.w);

    float s = x0.x*v0.x + x0.y*v0.y + x0.z*v0.z + x0.w*v0.w
            + x1.x*v1.x + x1.y*v1.y + x1.z*v1.z + x1.w*v1.w;
    #pragma unroll
    for (int o = 16; o; o >>= 1) s += __shfl_xor_sync(0xffffffffu, s, o);
    if (lane == 0) g_p[w] = s;
}

// K2: first ZB blocks zero `out` (overlaps with latency-bound score blocks);
//     remaining blocks score 4 edges/thread, global max, candidate-collect.
__global__ void k_score_zero(const int* __restrict__ src, const int* __restrict__ dst,
                             int E, float* __restrict__ out, int n_out4, int ZB) {
    if (blockIdx.x < ZB) {
        float4* o4 = (float4*)out;
        const float4 z = make_float4(0.f, 0.f, 0.f, 0.f);
        int tid  = blockIdx.x * blockDim.x + threadIdx.x;
        int nthr = ZB * blockDim.x;
        for (int i = tid; i < n_out4; i += nthr) o4[i] = z;
        return;
    }
    int i4   = (blockIdx.x - ZB) * blockDim.x + threadIdx.x;
    int base = i4 * 4;
    float sc0 = -INFINITY, sc1 = -INFINITY, sc2 = -INFINITY, sc3 = -INFINITY;
    if (base + 3 < E) {
        int4 s4 = ((const int4*)src)[i4];
        int4 d4 = ((const int4*)dst)[i4];
        float ps0 = g_p[s4.x], ps1 = g_p[s4.y], ps2 = g_p[s4.z], ps3 = g_p[s4.w];
        float pd0 = g_p[d4.x], pd1 = g_p[d4.y], pd2 = g_p[d4.z], pd3 = g_p[d4.w];
        sc0 = lrelu(ps0 + pd0);
        sc1 = lrelu(ps1 + pd1);
        sc2 = lrelu(ps2 + pd2);
        sc3 = lrelu(ps3 + pd3);
    } else if (base < E) {
        if (base + 0 < E) sc0 = lrelu(g_p[src[base + 0]] + g_p[dst[base + 0]]);
        if (base + 1 < E) sc1 = lrelu(g_p[src[base + 1]] + g_p[dst[base + 1]]);
        if (base + 2 < E) sc2 = lrelu(g_p[src[base + 2]] + g_p[dst[base + 2]]);
    }
    float m = fmaxf(fmaxf(sc0, sc1), fmaxf(sc2, sc3));

    // Block max reduction.
    #pragma unroll
    for (int o = 16; o; o >>= 1) m = fmaxf(m, __shfl_xor_sync(0xffffffffu, m, o));
    __shared__ float sm[8];
    __shared__ unsigned int s_gmax;
    int lane = threadIdx.x & 31, wid = threadIdx.x >> 5;
    if (lane == 0) sm[wid] = m;
    __syncthreads();
    if (wid == 0 && lane == 0) {
        float bm = sm[0];
        #pragma unroll
        for (int k = 1; k < 8; ++k) bm = fmaxf(bm, sm[k]);
        unsigned int e = enc_f(bm);
        unsigned int old = atomicMax(&g_max_enc, e);
        s_gmax = old > e ? old : e;   // running global estimate (monotone <= final)
    }
    __syncthreads();

    // Conservative candidate collection: threshold <= final gmax - 87 => superset.
    float thr = dec_f(s_gmax) + EXP_CUT;
    if (fmaxf(fmaxf(sc0, sc1), fmaxf(sc2, sc3)) > thr) {
        if (sc0 > thr) { int p = atomicAdd(&g_nsurv, 1); if (p < CAP) { g_surv[p] = base;     g_sval[p] = sc0; } }
        if (sc1 > thr) { int p = atomicAdd(&g_nsurv, 1); if (p < CAP) { g_surv[p] = base + 1; g_sval[p] = sc1; } }
        if (sc2 > thr) { int p = atomicAdd(&g_nsurv, 1); if (p < CAP) { g_surv[p] = base + 2; g_sval[p] = sc2; } }
        if (sc3 > thr) { int p = atomicAdd(&g_nsurv, 1); if (p < CAP) { g_surv[p] = base + 3; g_sval[p] = sc3; } }
    }
}

// K3: single block — parallel filter + smem compaction, then scatter survivors.
__global__ void k_finish(const float* __restrict__ x, const int* __restrict__ src,
                         const int* __restrict__ dst, float* __restrict__ out) {
    __shared__ int   s_sid[SCAP];   // surviving edge ids
    __shared__ float s_sw[SCAP];    // their exp(z) numerators
    __shared__ int   s_cnt;
    __shared__ float s_red[32];
    __shared__ float s_sum;

    int n = g_nsurv; if (n > CAP) n = CAP;
    float gmax = dec_f(g_max_enc);
    if (threadIdx.x == 0) s_cnt = 0;
    __syncthreads();

    // Parallel sweep: sumexp + compact true survivors (z > EXP_CUT vs FINAL max).
    float part = 0.f;
    for (int k = threadIdx.x; k < n; k += blockDim.x) {
        float z = g_sval[k] - gmax;
        if (z > EXP_CUT) {
            float ex = __expf(z);
            part += ex;
            int p = atomicAdd(&s_cnt, 1);
            if (p < SCAP) { s_sid[p] = g_surv[k]; s_sw[p] = ex; }
        }
    }
    #pragma unroll
    for (int o = 16; o; o >>= 1) part += __shfl_xor_sync(0xffffffffu, part, o);
    int lane = threadIdx.x & 31, wid = threadIdx.x >> 5;
    if (lane == 0) s_red[wid] = part;
    __syncthreads();
    if (wid == 0) {
        int nw = blockDim.x >> 5;
        part = (lane < nw) ? s_red[lane] : 0.f;
        #pragma unroll
        for (int o = 16; o; o >>= 1) part += __shfl_xor_sync(0xffffffffu, part, o);
        if (lane == 0) s_sum = part;
    }
    __syncthreads();

    int   ns      = s_cnt < SCAP ? s_cnt : SCAP;
    float inv_sum = 1.f / s_sum;

    // Scatter: one warp per surviving edge (list is tiny).
    int warp = threadIdx.x >> 5, nwarps = blockDim.x >> 5;
    for (int k = warp; k < ns; k += nwarps) {
        float wgt = s_sw[k] * inv_sum;
        int e  = s_sid[k];
        int si = src[e], di = dst[e];

        const float4* xi = (const float4*)(x + (size_t)si * D);
        const float4* xj = (const float4*)(x + (size_t)di * D);
        float4 a0 = xi[lane], a1 = xi[lane + 32];
        float4 b0 = xj[lane], b1 = xj[lane + 32];
        float t, d2 = 0.f;
        t = a0.x - b0.x; d2 += t * t;
        t = a0.y - b0.y; d2 += t * t;
        t = a0.z - b0.z; d2 += t * t;
        t = a0.w - b0.w; d2 += t * t;
        t = a1.x - b1.x; d2 += t * t;
        t = a1.y - b1.y; d2 += t * t;
        t = a1.z - b1.z; d2 += t * t;
        t = a1.w - b1.w; d2 += t * t;
        #pragma unroll
        for (int o = 16; o; o >>= 1) d2 += __shfl_xor_sync(0xffffffffu, d2, o);

        float c = wgt * sqrtf(d2);
        float* op = out + (size_t)si * D;
        asm volatile("red.global.add.v4.f32 [%0], {%1,%2,%3,%4};" ::
            "l"(op + lane * 4), "f"(c * b0.x), "f"(c * b0.y), "f"(c * b0.z), "f"(c * b0.w)
            : "memory");
        asm volatile("red.global.add.v4.f32 [%0], {%1,%2,%3,%4};" ::
            "l"(op + (lane + 32) * 4), "f"(c * b1.x), "f"(c * b1.y), "f"(c * b1.z), "f"(c * b1.w)
            : "memory");
    }
}

extern "C" void kernel_launch(void* const* d_in, const int* in_sizes, int n_in,
                              void* d_out, int out_size) {
    const float* x  = (const float*)d_in[0];
    const int*   ei = (const int*)  d_in[1];
    const float* W  = (const float*)d_in[2];
    const float* a  = (const float*)d_in[3];
    float* out = (float*)d_out;

    int N = in_sizes[0] / D;
    int E = in_sizes[1] / 2;
    const int* src = ei;        // edge_index[0]
    const int* dst = ei + E;    // edge_index[1]

    int e4 = (E + 3) / 4;
    int score_blocks = (e4 + 255) / 256;
    const int ZB = 512;
    int n_out4 = out_size / 4;

    k_init<<<4, D>>>(W, a);
    k_dot<<<(N * 32 + 255) / 256, 256>>>(x, N);
    k_score_zero<<<score_blocks + ZB, 256>>>(src, dst, E, out, n_out4, ZB);
    k_finish<<<1, 1024>>>(x, src, dst, out);
}

// round 6
// speedup vs baseline: 1.0422x; 1.0422x over previous
#include <cuda_runtime.h>
#include <math.h>

#define D 256
#define MAX_N 65536
#define EXP_CUT (-87.0f)   // exp underflow cut
#define CAP 16384          // global candidate list capacity
#define SCAP 1024          // smem survivor list capacity (true survivors ~O(10))

// Persistent device scratch.
__device__ float        g_v[D];       // v = W^T a
__device__ float        g_p[MAX_N];   // p[n] = x[n] . v
__device__ unsigned int g_max_enc;    // order-preserving encoded global max
__device__ int          g_nsurv;      // # candidate edges
__device__ int          g_done;       // completed-block counter
__device__ int          g_surv[CAP];  // candidate edge ids
__device__ float        g_sval[CAP];  // candidate scores

__device__ __forceinline__ unsigned int enc_f(float f) {
    unsigned int u = __float_as_uint(f);
    return (u & 0x80000000u) ? ~u : (u | 0x80000000u);
}
__device__ __forceinline__ float dec_f(unsigned int u) {
    return __uint_as_float((u & 0x80000000u) ? (u & 0x7FFFFFFFu) : ~u);
}
#define ENC_NEG_INF 0x007FFFFFu   // enc_f(-inf)

__device__ __forceinline__ float lrelu(float s) { return s > 0.f ? s : 0.2f * s; }

// K0: v[i] = sum_o a[o]*W[o,i].  1024 threads: 4 segments x 64 rows, smem reduce.
__global__ void k_init(const float* __restrict__ W, const float* __restrict__ a) {
    __shared__ float red[4][D];
    int i   = threadIdx.x & (D - 1);
    int seg = threadIdx.x >> 8;            // 0..3
    float s = 0.f;
    int o0 = seg * 64;
    #pragma unroll 8
    for (int o = o0; o < o0 + 64; ++o) s = fmaf(__ldg(a + o), __ldg(W + o * D + i), s);
    red[seg][i] = s;
    __syncthreads();
    if (seg == 0) {
        g_v[i] = red[0][i] + red[1][i] + red[2][i] + red[3][i];
        if (i == 0) { g_max_enc = ENC_NEG_INF; g_nsurv = 0; g_done = 0; }
    }
}

// K1: one warp per node — p[n] = x[n] . v.
__global__ void k_dot(const float* __restrict__ x, int N) {
    int w = (blockIdx.x * blockDim.x + threadIdx.x) >> 5;
    if (w >= N) return;
    int lane = threadIdx.x & 31;
    const float4* xr = (const float4*)(x + (size_t)w * D);
    const float4* vr = (const float4*)g_v;
    float4 x0 = xr[lane], x1 = xr[lane + 32];
    float4 v0 = vr[lane], v1 = vr[lane + 32];
    float s = x0.x*v0.x + x0.y*v0.y + x0.z*v0.z + x0.w*v0.w
            + x1.x*v1.x + x1.y*v1.y + x1.z*v1.z + x1.w*v1.w;
    #pragma unroll
    for (int o = 16; o; o >>= 1) s += __shfl_xor_sync(0xffffffffu, s, o);
    if (lane == 0) g_p[w] = s;
}

// K2: fused mega-kernel.
//  - blocks [0, ZB)            : zero `out`
//  - blocks [ZB, ZB+score_blks): score 4 edges/thread, global max, candidate-collect
//  - the LAST block to finish  : filter candidates vs final max, sumexp, scatter
__global__ void k_score_zero(const int* __restrict__ src, const int* __restrict__ dst,
                             int E, const float* __restrict__ x,
                             float* __restrict__ out, int n_out4, int ZB) {
    if (blockIdx.x < ZB) {
        float4* o4 = (float4*)out;
        const float4 z = make_float4(0.f, 0.f, 0.f, 0.f);
        int tid  = blockIdx.x * blockDim.x + threadIdx.x;
        int nthr = ZB * blockDim.x;
        for (int i = tid; i < n_out4; i += nthr) o4[i] = z;
    } else {
        int i4   = (blockIdx.x - ZB) * blockDim.x + threadIdx.x;
        int base = i4 * 4;
        float sc0 = -INFINITY, sc1 = -INFINITY, sc2 = -INFINITY, sc3 = -INFINITY;
        if (base + 3 < E) {
            int4 s4 = ((const int4*)src)[i4];
            int4 d4 = ((const int4*)dst)[i4];
            float ps0 = g_p[s4.x], ps1 = g_p[s4.y], ps2 = g_p[s4.z], ps3 = g_p[s4.w];
            float pd0 = g_p[d4.x], pd1 = g_p[d4.y], pd2 = g_p[d4.z], pd3 = g_p[d4.w];
            sc0 = lrelu(ps0 + pd0);
            sc1 = lrelu(ps1 + pd1);
            sc2 = lrelu(ps2 + pd2);
            sc3 = lrelu(ps3 + pd3);
        } else if (base < E) {
            if (base + 0 < E) sc0 = lrelu(g_p[src[base + 0]] + g_p[dst[base + 0]]);
            if (base + 1 < E) sc1 = lrelu(g_p[src[base + 1]] + g_p[dst[base + 1]]);
            if (base + 2 < E) sc2 = lrelu(g_p[src[base + 2]] + g_p[dst[base + 2]]);
        }
        float m = fmaxf(fmaxf(sc0, sc1), fmaxf(sc2, sc3));

        // Block max -> global atomicMax; keep running estimate for collection.
        #pragma unroll
        for (int o = 16; o; o >>= 1) m = fmaxf(m, __shfl_xor_sync(0xffffffffu, m, o));
        __shared__ float sm[8];
        __shared__ unsigned int s_gmax;
        int lane = threadIdx.x & 31, wid = threadIdx.x >> 5;
        if (lane == 0) sm[wid] = m;
        __syncthreads();
        if (wid == 0 && lane == 0) {
            float bm = sm[0];
            #pragma unroll
            for (int k = 1; k < 8; ++k) bm = fmaxf(bm, sm[k]);
            unsigned int e = enc_f(bm);
            unsigned int old = atomicMax(&g_max_enc, e);
            s_gmax = old > e ? old : e;   // monotone <= final max
        }
        __syncthreads();

        // Conservative candidate collection (superset of nonzero-weight edges).
        float thr = dec_f(s_gmax) + EXP_CUT;
        if (fmaxf(fmaxf(sc0, sc1), fmaxf(sc2, sc3)) > thr) {
            if (sc0 > thr) { int p = atomicAdd(&g_nsurv, 1); if (p < CAP) { g_surv[p] = base;     g_sval[p] = sc0; } }
            if (sc1 > thr) { int p = atomicAdd(&g_nsurv, 1); if (p < CAP) { g_surv[p] = base + 1; g_sval[p] = sc1; } }
            if (sc2 > thr) { int p = atomicAdd(&g_nsurv, 1); if (p < CAP) { g_surv[p] = base + 2; g_sval[p] = sc2; } }
            if (sc3 > thr) { int p = atomicAdd(&g_nsurv, 1); if (p < CAP) { g_surv[p] = base + 3; g_sval[p] = sc3; } }
        }
    }

    // ---- last-block election ----
    __threadfence();
    __shared__ int s_last;
    if (threadIdx.x == 0) s_last = (atomicAdd(&g_done, 1) == (int)gridDim.x - 1);
    __syncthreads();
    if (!s_last) return;

    // ---- finish (runs on exactly one block; all prior writes visible) ----
    __shared__ int   s_sid[SCAP];
    __shared__ float s_sw[SCAP];
    __shared__ int   s_cnt;
    __shared__ float s_red2[8];
    __shared__ float s_sum;

    int n = g_nsurv; if (n > CAP) n = CAP;
    float gmax = dec_f(g_max_enc);
    if (threadIdx.x == 0) s_cnt = 0;
    __syncthreads();

    float part = 0.f;
    for (int k = threadIdx.x; k < n; k += blockDim.x) {
        float z = g_sval[k] - gmax;
        if (z > EXP_CUT) {
            float ex = __expf(z);
            part += ex;
            int p = atomicAdd(&s_cnt, 1);
            if (p < SCAP) { s_sid[p] = g_surv[k]; s_sw[p] = ex; }
        }
    }
    #pragma unroll
    for (int o = 16; o; o >>= 1) part += __shfl_xor_sync(0xffffffffu, part, o);
    int lane = threadIdx.x & 31, wid = threadIdx.x >> 5;
    if (lane == 0) s_red2[wid] = part;
    __syncthreads();
    if (wid == 0) {
        part = (lane < (int)(blockDim.x >> 5)) ? s_red2[lane] : 0.f;
        #pragma unroll
        for (int o = 16; o; o >>= 1) part += __shfl_xor_sync(0xffffffffu, part, o);
        if (lane == 0) s_sum = part;
    }
    __syncthreads();

    int   ns      = s_cnt < SCAP ? s_cnt : SCAP;
    float inv_sum = 1.f / s_sum;

    int warp = threadIdx.x >> 5, nwarps = blockDim.x >> 5;
    for (int k = warp; k < ns; k += nwarps) {
        float wgt = s_sw[k] * inv_sum;
        int e  = s_sid[k];
        int si = src[e], di = dst[e];

        const float4* xi = (const float4*)(x + (size_t)si * D);
        const float4* xj = (const float4*)(x + (size_t)di * D);
        float4 a0 = xi[lane], a1 = xi[lane + 32];
        float4 b0 = xj[lane], b1 = xj[lane + 32];
        float t, d2 = 0.f;
        t = a0.x - b0.x; d2 += t * t;
        t = a0.y - b0.y; d2 += t * t;
        t = a0.z - b0.z; d2 += t * t;
        t = a0.w - b0.w; d2 += t * t;
        t = a1.x - b1.x; d2 += t * t;
        t = a1.y - b1.y; d2 += t * t;
        t = a1.z - b1.z; d2 += t * t;
        t = a1.w - b1.w; d2 += t * t;
        #pragma unroll
        for (int o = 16; o; o >>= 1) d2 += __shfl_xor_sync(0xffffffffu, d2, o);

        float c = wgt * sqrtf(d2);
        float* op = out + (size_t)si * D;
        asm volatile("red.global.add.v4.f32 [%0], {%1,%2,%3,%4};" ::
            "l"(op + lane * 4), "f"(c * b0.x), "f"(c * b0.y), "f"(c * b0.z), "f"(c * b0.w)
            : "memory");
        asm volatile("red.global.add.v4.f32 [%0], {%1,%2,%3,%4};" ::
            "l"(op + (lane + 32) * 4), "f"(c * b1.x), "f"(c * b1.y), "f"(c * b1.z), "f"(c * b1.w)
            : "memory");
    }
}

extern "C" void kernel_launch(void* const* d_in, const int* in_sizes, int n_in,
                              void* d_out, int out_size) {
    const float* x  = (const float*)d_in[0];
    const int*   ei = (const int*)  d_in[1];
    const float* W  = (const float*)d_in[2];
    const float* a  = (const float*)d_in[3];
    float* out = (float*)d_out;

    int N = in_sizes[0] / D;
    int E = in_sizes[1] / 2;
    const int* src = ei;        // edge_index[0]
    const int* dst = ei + E;    // edge_index[1]

    int e4 = (E + 3) / 4;
    int score_blocks = (e4 + 255) / 256;
    const int ZB = 512;
    int n_out4 = out_size / 4;

    k_init<<<1, 1024>>>(W, a);
    k_dot<<<(N * 32 + 255) / 256, 256>>>(x, N);
    k_score_zero<<<score_blocks + ZB, 256>>>(src, dst, E, x, out, n_out4, ZB);
}

// round 7
// speedup vs baseline: 1.1645x; 1.1174x over previous
#include <cuda_runtime.h>
#include <math.h>

#define D 256
#define MAX_N 65536
#define EXP_CUT (-87.0f)   // exp underflow cut
#define CAP 16384          // global candidate list capacity
#define SCAP 1024          // smem survivor list capacity (true survivors ~O(10))
#define ENC_NEG_INF 0x007FFFFFu   // enc_f(-inf)
#define VB 64              // k_init partial blocks

// Persistent device scratch (statics give first-call init; kernels self-reset).
__device__ float        g_v[D];          // v = W^T a
__device__ float        g_vp[VB][D];     // per-block partials of v
__device__ float        g_p[MAX_N];      // p[n] = x[n] . v
__device__ unsigned int g_max_enc = ENC_NEG_INF;
__device__ int          g_nsurv   = 0;   // # candidate edges
__device__ int          g_done0   = 0;   // k_init election counter
__device__ int          g_done1   = 0;   // k_score_zero election counter
__device__ int          g_surv[CAP];     // candidate edge ids
__device__ float        g_sval[CAP];     // candidate scores

__device__ __forceinline__ unsigned int enc_f(float f) {
    unsigned int u = __float_as_uint(f);
    return (u & 0x80000000u) ? ~u : (u | 0x80000000u);
}
__device__ __forceinline__ float dec_f(unsigned int u) {
    return __uint_as_float((u & 0x80000000u) ? (u & 0x7FFFFFFFu) : ~u);
}
__device__ __forceinline__ float lrelu(float s) { return s > 0.f ? s : 0.2f * s; }

// K0: 64 blocks x 256 threads. Block b: partial over 4 W-rows; last block reduces.
__global__ void k_init(const float* __restrict__ W, const float* __restrict__ a) {
    int i = threadIdx.x;                // 0..255 (column)
    int b = blockIdx.x;                 // 0..63
    int o0 = b * 4;
    float a0 = __ldg(a + o0), a1 = __ldg(a + o0 + 1);
    float a2 = __ldg(a + o0 + 2), a3 = __ldg(a + o0 + 3);
    float w0 = __ldg(W + (o0 + 0) * D + i);
    float w1 = __ldg(W + (o0 + 1) * D + i);
    float w2 = __ldg(W + (o0 + 2) * D + i);
    float w3 = __ldg(W + (o0 + 3) * D + i);
    g_vp[b][i] = (a0 * w0 + a1 * w1) + (a2 * w2 + a3 * w3);

    __threadfence();
    __shared__ int s_last;
    if (threadIdx.x == 0) s_last = (atomicAdd(&g_done0, 1) == VB - 1);
    __syncthreads();
    if (!s_last) return;

    float s = 0.f;
    #pragma unroll 16
    for (int k = 0; k < VB; ++k) s += g_vp[k][i];
    g_v[i] = s;
    if (threadIdx.x == 0) g_done0 = 0;   // self-reset for graph replay
}

// K1: one warp per node — p[n] = x[n] . v.
__global__ void k_dot(const float* __restrict__ x, int N) {
    int w = (blockIdx.x * blockDim.x + threadIdx.x) >> 5;
    if (w >= N) return;
    int lane = threadIdx.x & 31;
    const float4* xr = (const float4*)(x + (size_t)w * D);
    const float4* vr = (const float4*)g_v;
    float4 x0 = xr[lane], x1 = xr[lane + 32];
    float4 v0 = vr[lane], v1 = vr[lane + 32];
    float s = x0.x*v0.x + x0.y*v0.y + x0.z*v0.z + x0.w*v0.w
            + x1.x*v1.x + x1.y*v1.y + x1.z*v1.z + x1.w*v1.w;
    #pragma unroll
    for (int o = 16; o; o >>= 1) s += __shfl_xor_sync(0xffffffffu, s, o);
    if (lane == 0) g_p[w] = s;
}

// K2: fused mega-kernel.
//  - blocks [0, ZB)            : zero `out`
//  - blocks [ZB, ...)          : score 4 edges/thread, global max, candidate-collect
//  - the LAST block to finish  : filter vs final max, sumexp, scatter, self-reset
__global__ void k_score_zero(const int* __restrict__ src, const int* __restrict__ dst,
                             int E, const float* __restrict__ x,
                             float* __restrict__ out, int n_out4, int ZB) {
    if (blockIdx.x < ZB) {
        float4* o4 = (float4*)out;
        const float4 z = make_float4(0.f, 0.f, 0.f, 0.f);
        int tid  = blockIdx.x * blockDim.x + threadIdx.x;
        int nthr = ZB * blockDim.x;
        for (int i = tid; i < n_out4; i += nthr) o4[i] = z;
    } else {
        int i4   = (blockIdx.x - ZB) * blockDim.x + threadIdx.x;
        int base = i4 * 4;
        float sc0 = -INFINITY, sc1 = -INFINITY, sc2 = -INFINITY, sc3 = -INFINITY;
        if (base + 3 < E) {
            int4 s4 = ((const int4*)src)[i4];
            int4 d4 = ((const int4*)dst)[i4];
            float ps0 = g_p[s4.x], ps1 = g_p[s4.y], ps2 = g_p[s4.z], ps3 = g_p[s4.w];
            float pd0 = g_p[d4.x], pd1 = g_p[d4.y], pd2 = g_p[d4.z], pd3 = g_p[d4.w];
            sc0 = lrelu(ps0 + pd0);
            sc1 = lrelu(ps1 + pd1);
            sc2 = lrelu(ps2 + pd2);
            sc3 = lrelu(ps3 + pd3);
        } else if (base < E) {
            if (base + 0 < E) sc0 = lrelu(g_p[src[base + 0]] + g_p[dst[base + 0]]);
            if (base + 1 < E) sc1 = lrelu(g_p[src[base + 1]] + g_p[dst[base + 1]]);
            if (base + 2 < E) sc2 = lrelu(g_p[src[base + 2]] + g_p[dst[base + 2]]);
        }
        float m = fmaxf(fmaxf(sc0, sc1), fmaxf(sc2, sc3));

        #pragma unroll
        for (int o = 16; o; o >>= 1) m = fmaxf(m, __shfl_xor_sync(0xffffffffu, m, o));
        __shared__ float sm[8];
        __shared__ unsigned int s_gmax;
        int lane = threadIdx.x & 31, wid = threadIdx.x >> 5;
        if (lane == 0) sm[wid] = m;
        __syncthreads();
        if (wid == 0 && lane == 0) {
            float bm = sm[0];
            #pragma unroll
            for (int k = 1; k < 8; ++k) bm = fmaxf(bm, sm[k]);
            unsigned int e = enc_f(bm);
            unsigned int old = atomicMax(&g_max_enc, e);
            s_gmax = old > e ? old : e;   // running estimate, monotone <= final
        }
        __syncthreads();

        // Conservative candidate collection (superset of nonzero-weight edges).
        float thr = dec_f(s_gmax) + EXP_CUT;
        if (fmaxf(fmaxf(sc0, sc1), fmaxf(sc2, sc3)) > thr) {
            if (sc0 > thr) { int p = atomicAdd(&g_nsurv, 1); if (p < CAP) { g_surv[p] = base;     g_sval[p] = sc0; } }
            if (sc1 > thr) { int p = atomicAdd(&g_nsurv, 1); if (p < CAP) { g_surv[p] = base + 1; g_sval[p] = sc1; } }
            if (sc2 > thr) { int p = atomicAdd(&g_nsurv, 1); if (p < CAP) { g_surv[p] = base + 2; g_sval[p] = sc2; } }
            if (sc3 > thr) { int p = atomicAdd(&g_nsurv, 1); if (p < CAP) { g_surv[p] = base + 3; g_sval[p] = sc3; } }
        }
    }

    // ---- last-block election ----
    __threadfence();
    __shared__ int s_last;
    if (threadIdx.x == 0) s_last = (atomicAdd(&g_done1, 1) == (int)gridDim.x - 1);
    __syncthreads();
    if (!s_last) return;

    // ---- finish (exactly one block; all prior writes visible) ----
    __shared__ int   s_sid[SCAP];
    __shared__ float s_sw[SCAP];
    __shared__ int   s_cnt;
    __shared__ float s_red2[8];
    __shared__ float s_sum;

    int n = g_nsurv; if (n > CAP) n = CAP;
    float gmax = dec_f(g_max_enc);
    if (threadIdx.x == 0) s_cnt = 0;
    __syncthreads();

    float part = 0.f;
    for (int k = threadIdx.x; k < n; k += blockDim.x) {
        float z = g_sval[k] - gmax;
        if (z > EXP_CUT) {
            float ex = __expf(z);
            part += ex;
            int p = atomicAdd(&s_cnt, 1);
            if (p < SCAP) { s_sid[p] = g_surv[k]; s_sw[p] = ex; }
        }
    }
    #pragma unroll
    for (int o = 16; o; o >>= 1) part += __shfl_xor_sync(0xffffffffu, part, o);
    int lane = threadIdx.x & 31, wid = threadIdx.x >> 5;
    if (lane == 0) s_red2[wid] = part;
    __syncthreads();
    if (wid == 0) {
        part = (lane < (int)(blockDim.x >> 5)) ? s_red2[lane] : 0.f;
        #pragma unroll
        for (int o = 16; o; o >>= 1) part += __shfl_xor_sync(0xffffffffu, part, o);
        if (lane == 0) s_sum = part;
    }
    __syncthreads();

    int   ns      = s_cnt < SCAP ? s_cnt : SCAP;
    float inv_sum = 1.f / s_sum;

    int warp = threadIdx.x >> 5, nwarps = blockDim.x >> 5;
    for (int k = warp; k < ns; k += nwarps) {
        float wgt = s_sw[k] * inv_sum;
        int e  = s_sid[k];
        int si = src[e], di = dst[e];

        const float4* xi = (const float4*)(x + (size_t)si * D);
        const float4* xj = (const float4*)(x + (size_t)di * D);
        float4 a0 = xi[lane], a1 = xi[lane + 32];
        float4 b0 = xj[lane], b1 = xj[lane + 32];
        float t, d2 = 0.f;
        t = a0.x - b0.x; d2 += t * t;
        t = a0.y - b0.y; d2 += t * t;
        t = a0.z - b0.z; d2 += t * t;
        t = a0.w - b0.w; d2 += t * t;
        t = a1.x - b1.x; d2 += t * t;
        t = a1.y - b1.y; d2 += t * t;
        t = a1.z - b1.z; d2 += t * t;
        t = a1.w - b1.w; d2 += t * t;
        #pragma unroll
        for (int o = 16; o; o >>= 1) d2 += __shfl_xor_sync(0xffffffffu, d2, o);

        float c = wgt * sqrtf(d2);
        float* op = out + (size_t)si * D;
        asm volatile("red.global.add.v4.f32 [%0], {%1,%2,%3,%4};" ::
            "l"(op + lane * 4), "f"(c * b0.x), "f"(c * b0.y), "f"(c * b0.z), "f"(c * b0.w)
            : "memory");
        asm volatile("red.global.add.v4.f32 [%0], {%1,%2,%3,%4};" ::
            "l"(op + (lane + 32) * 4), "f"(c * b1.x), "f"(c * b1.y), "f"(c * b1.z), "f"(c * b1.w)
            : "memory");
    }

    // ---- self-reset for graph replay ----
    __syncthreads();
    if (threadIdx.x == 0) {
        g_max_enc = ENC_NEG_INF;
        g_nsurv   = 0;
        g_done1   = 0;
    }
}

extern "C" void kernel_launch(void* const* d_in, const int* in_sizes, int n_in,
                              void* d_out, int out_size) {
    const float* x  = (const float*)d_in[0];
    const int*   ei = (const int*)  d_in[1];
    const float* W  = (const float*)d_in[2];
    const float* a  = (const float*)d_in[3];
    float* out = (float*)d_out;

    int N = in_sizes[0] / D;
    int E = in_sizes[1] / 2;
    const int* src = ei;        // edge_index[0]
    const int* dst = ei + E;    // edge_index[1]

    int e4 = (E + 3) / 4;
    int score_blocks = (e4 + 255) / 256;
    const int ZB = 512;
    int n_out4 = out_size / 4;

    k_init<<<VB, D>>>(W, a);
    k_dot<<<(N * 32 + 255) / 256, 256>>>(x, N);
    k_score_zero<<<score_blocks + ZB, 256>>>(src, dst, E, x, out, n_out4, ZB);
}